// round 2
// baseline (speedup 1.0000x reference)
#include <cuda_runtime.h>
#include <cuda_bf16.h>
#include <cstdint>

// Problem constants
#define BB 512
#define NN 2048
#define FF 64
#define TT 4
#define H1 64
#define H2 32

#define BT 128            // batch rows per block
#define PAIRS (BT/2)      // 64 row-pairs
#define THREADS 256

typedef unsigned long long ull;

__device__ __forceinline__ ull pk2(float lo, float hi) {
    ull r; asm("mov.b64 %0, {%1, %2};" : "=l"(r) : "f"(lo), "f"(hi)); return r;
}
__device__ __forceinline__ float2 upk2(ull v) {
    float2 r; asm("mov.b64 {%0, %1}, %2;" : "=f"(r.x), "=f"(r.y) : "l"(v)); return r;
}
__device__ __forceinline__ void fma2(ull& d, ull a, ull b) {
    asm("fma.rn.f32x2 %0, %1, %2, %0;" : "+l"(d) : "l"(a), "l"(b));
}
__device__ __forceinline__ float silu(float v) {
    return v / (1.0f + __expf(-v));
}

struct Smem {
    float2 Xs[PAIRS][FF];     // pair-interleaved x: Xs[p][k] = (x[2p][k], x[2p+1][k])  32 KB
    float2 H1s[PAIRS][H1];    // pair-interleaved hidden1                               32 KB
    float  W0t[FF][68];       // transposed + padded: W0t[k][j] = w0[t][j][k]           17 KB
    float  W1t[H1][36];       // transposed + padded: W1t[j][g] = w1[t][g][j]            9 KB
    float  b0s[H1];
    float  b1s[H2];
    float  w2s[H2];
    float  b2s;
};

__global__ void zero_out_kernel(float* __restrict__ out) {
    out[threadIdx.x] = 0.0f;
}

__global__ __launch_bounds__(THREADS, 2)
void bpnn_kernel(const float* __restrict__ x,
                 const int*   __restrict__ atomic_numbers,
                 const float* __restrict__ w0, const float* __restrict__ b0,
                 const float* __restrict__ w1, const float* __restrict__ b1,
                 const float* __restrict__ w2, const float* __restrict__ b2,
                 float* __restrict__ out)
{
    extern __shared__ char smem_raw[];
    Smem& s = *reinterpret_cast<Smem*>(smem_raw);

    const int n   = blockIdx.x;          // atom index 0..2047
    const int b0r = blockIdx.y * BT;     // batch tile base row
    const int tid = threadIdx.x;

    const int t = atomic_numbers[n];

    // ---- load weights (transposed) ----
    const float* w0p = w0 + t * H1 * FF;           // [j][k]
    #pragma unroll
    for (int it = 0; it < (H1*FF)/THREADS; ++it) {
        int idx = tid + it * THREADS;              // idx = j*64 + k
        int j = idx >> 6, k = idx & 63;
        s.W0t[k][j] = w0p[idx];
    }
    const float* w1p = w1 + t * H2 * H1;           // [g][j]
    #pragma unroll
    for (int it = 0; it < (H2*H1)/THREADS; ++it) {
        int idx = tid + it * THREADS;              // idx = g*64 + j
        int g = idx >> 6, j = idx & 63;
        s.W1t[j][g] = w1p[idx];
    }
    if (tid < H1) s.b0s[tid] = b0[t * H1 + tid];
    if (tid < H2) { s.b1s[tid] = b1[t * H2 + tid]; s.w2s[tid] = w2[t * H2 + tid]; }
    if (tid == 0) s.b2s = b2[t];

    // ---- load x tile, pair-interleaved ----
    // tasks: 64 pairs x 16 k-quads = 1024
    #pragma unroll
    for (int it = 0; it < 4; ++it) {
        int task = tid + it * THREADS;
        int kq = task & 15;
        int p  = task >> 4;
        size_t base0 = ((size_t)(b0r + 2*p)     * NN + n) * FF + kq * 4;
        size_t base1 = ((size_t)(b0r + 2*p + 1) * NN + n) * FF + kq * 4;
        float4 a = *reinterpret_cast<const float4*>(&x[base0]);
        float4 c = *reinterpret_cast<const float4*>(&x[base1]);
        float2* dst = &s.Xs[p][kq * 4];
        dst[0] = make_float2(a.x, c.x);
        dst[1] = make_float2(a.y, c.y);
        dst[2] = make_float2(a.z, c.z);
        dst[3] = make_float2(a.w, c.w);
    }
    __syncthreads();

    // ================= GEMM1: H1s = silu(Xs @ W0^T + b0) =================
    // thread tile: 4 row-pairs x 4 cols.  cg = col group, pg = pair group.
    {
        const int cg = tid & 15;     // 16 col groups  (j = cg*4 .. cg*4+3)
        const int pg = tid >> 4;     // 16 pair groups (p = pg*4 .. pg*4+3)

        ull acc[4][4];
        #pragma unroll
        for (int jj = 0; jj < 4; ++jj) {
            float bj = s.b0s[cg * 4 + jj];
            ull bp = pk2(bj, bj);
            #pragma unroll
            for (int pi = 0; pi < 4; ++pi) acc[pi][jj] = bp;
        }

        #pragma unroll 4
        for (int k = 0; k < FF; k += 2) {
            ulonglong2 xp[4];
            #pragma unroll
            for (int pi = 0; pi < 4; ++pi)
                xp[pi] = *reinterpret_cast<const ulonglong2*>(&s.Xs[pg * 4 + pi][k]);

            float4 wa = *reinterpret_cast<const float4*>(&s.W0t[k][cg * 4]);
            float4 wb = *reinterpret_cast<const float4*>(&s.W0t[k + 1][cg * 4]);
            ull wpa[4] = { pk2(wa.x, wa.x), pk2(wa.y, wa.y), pk2(wa.z, wa.z), pk2(wa.w, wa.w) };
            ull wpb[4] = { pk2(wb.x, wb.x), pk2(wb.y, wb.y), pk2(wb.z, wb.z), pk2(wb.w, wb.w) };

            #pragma unroll
            for (int pi = 0; pi < 4; ++pi) {
                #pragma unroll
                for (int jj = 0; jj < 4; ++jj) {
                    fma2(acc[pi][jj], xp[pi].x, wpa[jj]);
                    fma2(acc[pi][jj], xp[pi].y, wpb[jj]);
                }
            }
        }

        #pragma unroll
        for (int pi = 0; pi < 4; ++pi) {
            #pragma unroll
            for (int jj = 0; jj < 4; ++jj) {
                float2 v = upk2(acc[pi][jj]);
                v.x = silu(v.x);
                v.y = silu(v.y);
                s.H1s[pg * 4 + pi][cg * 4 + jj] = v;
            }
        }
    }
    __syncthreads();

    // ============ GEMM2 + final dot: e = w2 . silu(H1s @ W1^T + b1) + b2 ============
    {
        const int cg2 = tid & 7;     // 8 g-groups   (g = cg2*4 .. cg2*4+3)
        const int pg2 = tid >> 3;    // 32 pair groups (p = pg2*2, pg2*2+1)

        ull acc2[2][4];
        #pragma unroll
        for (int gg = 0; gg < 4; ++gg) {
            float bg = s.b1s[cg2 * 4 + gg];
            ull bp = pk2(bg, bg);
            acc2[0][gg] = bp; acc2[1][gg] = bp;
        }

        #pragma unroll 4
        for (int j = 0; j < H1; j += 2) {
            ulonglong2 hp[2];
            #pragma unroll
            for (int pi = 0; pi < 2; ++pi)
                hp[pi] = *reinterpret_cast<const ulonglong2*>(&s.H1s[pg2 * 2 + pi][j]);

            float4 wa = *reinterpret_cast<const float4*>(&s.W1t[j][cg2 * 4]);
            float4 wb = *reinterpret_cast<const float4*>(&s.W1t[j + 1][cg2 * 4]);
            ull wpa[4] = { pk2(wa.x, wa.x), pk2(wa.y, wa.y), pk2(wa.z, wa.z), pk2(wa.w, wa.w) };
            ull wpb[4] = { pk2(wb.x, wb.x), pk2(wb.y, wb.y), pk2(wb.z, wb.z), pk2(wb.w, wb.w) };

            #pragma unroll
            for (int pi = 0; pi < 2; ++pi) {
                #pragma unroll
                for (int gg = 0; gg < 4; ++gg) {
                    fma2(acc2[pi][gg], hp[pi].x, wpa[gg]);
                    fma2(acc2[pi][gg], hp[pi].y, wpb[gg]);
                }
            }
        }

        float2 ep[2] = { make_float2(0.f, 0.f), make_float2(0.f, 0.f) };
        #pragma unroll
        for (int pi = 0; pi < 2; ++pi) {
            #pragma unroll
            for (int gg = 0; gg < 4; ++gg) {
                float2 v = upk2(acc2[pi][gg]);
                float wg = s.w2s[cg2 * 4 + gg];
                ep[pi].x += silu(v.x) * wg;
                ep[pi].y += silu(v.y) * wg;
            }
        }

        // reduce across the 8 g-groups (consecutive lanes within warp)
        #pragma unroll
        for (int off = 1; off < 8; off <<= 1) {
            #pragma unroll
            for (int pi = 0; pi < 2; ++pi) {
                ep[pi].x += __shfl_xor_sync(0xffffffffu, ep[pi].x, off);
                ep[pi].y += __shfl_xor_sync(0xffffffffu, ep[pi].y, off);
            }
        }

        if (cg2 == 0) {
            float bb = s.b2s;
            #pragma unroll
            for (int pi = 0; pi < 2; ++pi) {
                int p = pg2 * 2 + pi;
                int r = b0r + 2 * p;
                atomicAdd(&out[r],     ep[pi].x + bb);
                atomicAdd(&out[r + 1], ep[pi].y + bb);
            }
        }
    }
}

extern "C" void kernel_launch(void* const* d_in, const int* in_sizes, int n_in,
                              void* d_out, int out_size)
{
    const float* x  = (const float*)d_in[0];
    const int*   an = (const int*)  d_in[1];
    const float* w0 = (const float*)d_in[2];
    const float* b0 = (const float*)d_in[3];
    const float* w1 = (const float*)d_in[4];
    const float* b1 = (const float*)d_in[5];
    const float* w2 = (const float*)d_in[6];
    const float* b2 = (const float*)d_in[7];
    float* out = (float*)d_out;

    static_assert(sizeof(Smem) < 96 * 1024, "smem layout too big");
    cudaFuncSetAttribute(bpnn_kernel,
                         cudaFuncAttributeMaxDynamicSharedMemorySize,
                         (int)sizeof(Smem));

    zero_out_kernel<<<1, BB>>>(out);

    dim3 grid(NN, BB / BT);   // 2048 atoms x 4 batch tiles
    bpnn_kernel<<<grid, THREADS, sizeof(Smem)>>>(x, an, w0, b0, w1, b1, w2, b2, out);
}

// round 4
// speedup vs baseline: 3.0733x; 3.0733x over previous
#include <cuda_runtime.h>
#include <cuda_bf16.h>
#include <cstdint>

#define BB 512
#define NN 2048
#define FF 64
#define TT 4
#define H1 64
#define H2 32
#define BT 128
#define THREADS 128
#define PADX 68          // floats per smem row (68*4 = 272 B, 16B-aligned, conflict-free)

struct Smem {
    float Xs[BT][PADX];     // x tile (tf32 bits); reused as H1 after GEMM1
    float W0s[H1][PADX];    // W0[t] as [out][in] (tf32 bits)
    float W1s[H2][PADX];    // W1[t] as [out][in] (tf32 bits)
    float b0s[H1];
    float b1s[H2];
    float w2s[H2];
    float b2s;
};

static __device__ __forceinline__ uint32_t f2tf32(float f) {
    uint32_t r; asm("cvt.rna.tf32.f32 %0, %1;" : "=r"(r) : "f"(f)); return r;
}
static __device__ __forceinline__ float silu_t(float v) {
    float t; asm("tanh.approx.f32 %0, %1;" : "=f"(t) : "f"(0.5f * v));
    return 0.5f * v * (1.0f + t);
}
static __device__ __forceinline__ void mma8(float* d, const uint32_t* a,
                                            uint32_t b0r_, uint32_t b1r_) {
    asm volatile(
        "mma.sync.aligned.m16n8k8.row.col.f32.tf32.tf32.f32 "
        "{%0,%1,%2,%3}, {%4,%5,%6,%7}, {%8,%9}, {%0,%1,%2,%3};"
        : "+f"(d[0]), "+f"(d[1]), "+f"(d[2]), "+f"(d[3])
        : "r"(a[0]), "r"(a[1]), "r"(a[2]), "r"(a[3]), "r"(b0r_), "r"(b1r_));
}

__global__ void zero_out_kernel(float* __restrict__ out) {
    out[threadIdx.x] = 0.0f;
}

__global__ __launch_bounds__(THREADS)
void bpnn_mma_kernel(const float* __restrict__ x,
                     const int*   __restrict__ atomic_numbers,
                     const float* __restrict__ w0, const float* __restrict__ b0,
                     const float* __restrict__ w1, const float* __restrict__ b1,
                     const float* __restrict__ w2, const float* __restrict__ b2,
                     float* __restrict__ out)
{
    extern __shared__ char smem_raw[];
    Smem& s = *reinterpret_cast<Smem*>(smem_raw);

    const int tid = threadIdx.x;
    const int wid = tid >> 5;
    const int lid = tid & 31;
    const int gid = lid >> 2;     // groupID (0..7)
    const int tig = lid & 3;      // thread-in-group (0..3)
    const int n   = blockIdx.x;
    const int b0row = blockIdx.y * BT;

    const int t = atomic_numbers[n];

    // ---- stage W0 [64x64] as tf32 ----
    {
        const float* w0p = w0 + t * H1 * FF;
        #pragma unroll
        for (int it = 0; it < 8; ++it) {               // 1024 float4 tasks
            int task = it * THREADS + tid;
            int row = task >> 4, q = task & 15;
            float4 v = *reinterpret_cast<const float4*>(&w0p[row * FF + q * 4]);
            float4 o;
            o.x = __uint_as_float(f2tf32(v.x)); o.y = __uint_as_float(f2tf32(v.y));
            o.z = __uint_as_float(f2tf32(v.z)); o.w = __uint_as_float(f2tf32(v.w));
            *reinterpret_cast<float4*>(&s.W0s[row][q * 4]) = o;
        }
    }
    // ---- stage W1 [32x64] as tf32 ----
    {
        const float* w1p = w1 + t * H2 * H1;
        #pragma unroll
        for (int it = 0; it < 4; ++it) {               // 512 float4 tasks
            int task = it * THREADS + tid;
            int row = task >> 4, q = task & 15;
            float4 v = *reinterpret_cast<const float4*>(&w1p[row * H1 + q * 4]);
            float4 o;
            o.x = __uint_as_float(f2tf32(v.x)); o.y = __uint_as_float(f2tf32(v.y));
            o.z = __uint_as_float(f2tf32(v.z)); o.w = __uint_as_float(f2tf32(v.w));
            *reinterpret_cast<float4*>(&s.W1s[row][q * 4]) = o;
        }
    }
    if (tid < H1) s.b0s[tid] = b0[t * H1 + tid];
    if (tid < H2) { s.b1s[tid] = b1[t * H2 + tid]; s.w2s[tid] = w2[t * H2 + tid]; }
    if (tid == 0) s.b2s = b2[t];

    // ---- stage x tile [128 x 64] as tf32 ----
    #pragma unroll
    for (int it = 0; it < 16; ++it) {                  // 2048 float4 tasks
        int task = it * THREADS + tid;
        int row = task >> 4, q = task & 15;
        size_t g = ((size_t)(b0row + row) * NN + n) * FF + q * 4;
        float4 v = *reinterpret_cast<const float4*>(&x[g]);
        float4 o;
        o.x = __uint_as_float(f2tf32(v.x)); o.y = __uint_as_float(f2tf32(v.y));
        o.z = __uint_as_float(f2tf32(v.z)); o.w = __uint_as_float(f2tf32(v.w));
        *reinterpret_cast<float4*>(&s.Xs[row][q * 4]) = o;
    }
    __syncthreads();

    const int r0 = wid * 32;    // warp's private 32-row slice

    // ================= GEMM1: D1[32x64] = X . W0^T (per warp) =================
    float acc[2][8][4];
    #pragma unroll
    for (int mt = 0; mt < 2; ++mt)
        #pragma unroll
        for (int nt = 0; nt < 8; ++nt)
            #pragma unroll
            for (int c = 0; c < 4; ++c) acc[mt][nt][c] = 0.0f;

    #pragma unroll
    for (int kt = 0; kt < 8; ++kt) {
        uint32_t a[2][4];
        #pragma unroll
        for (int mt = 0; mt < 2; ++mt) {
            int ar = r0 + mt * 16 + gid;
            a[mt][0] = __float_as_uint(s.Xs[ar    ][kt * 8 + tig]);
            a[mt][1] = __float_as_uint(s.Xs[ar + 8][kt * 8 + tig]);
            a[mt][2] = __float_as_uint(s.Xs[ar    ][kt * 8 + tig + 4]);
            a[mt][3] = __float_as_uint(s.Xs[ar + 8][kt * 8 + tig + 4]);
        }
        #pragma unroll
        for (int nt = 0; nt < 8; ++nt) {
            uint32_t bb0 = __float_as_uint(s.W0s[nt * 8 + gid][kt * 8 + tig]);
            uint32_t bb1 = __float_as_uint(s.W0s[nt * 8 + gid][kt * 8 + tig + 4]);
            mma8(acc[0][nt], a[0], bb0, bb1);
            mma8(acc[1][nt], a[1], bb0, bb1);
        }
    }

    // ---- epilogue 1: H1 = tf32(silu(D1 + b0)) back into Xs (warp-private rows) ----
    #pragma unroll
    for (int mt = 0; mt < 2; ++mt) {
        #pragma unroll
        for (int nt = 0; nt < 8; ++nt) {
            int c0 = nt * 8 + 2 * tig;
            float bc0 = s.b0s[c0], bc1 = s.b0s[c0 + 1];
            int rlo = r0 + mt * 16 + gid;
            float v0 = __uint_as_float(f2tf32(silu_t(acc[mt][nt][0] + bc0)));
            float v1 = __uint_as_float(f2tf32(silu_t(acc[mt][nt][1] + bc1)));
            float v2 = __uint_as_float(f2tf32(silu_t(acc[mt][nt][2] + bc0)));
            float v3 = __uint_as_float(f2tf32(silu_t(acc[mt][nt][3] + bc1)));
            *reinterpret_cast<float2*>(&s.Xs[rlo    ][c0]) = make_float2(v0, v1);
            *reinterpret_cast<float2*>(&s.Xs[rlo + 8][c0]) = make_float2(v2, v3);
        }
    }
    __syncwarp();

    // ================= GEMM2: D2[32x32] = H1 . W1^T (per warp) =================
    float acc2[2][4][4];
    #pragma unroll
    for (int mt = 0; mt < 2; ++mt)
        #pragma unroll
        for (int nt = 0; nt < 4; ++nt)
            #pragma unroll
            for (int c = 0; c < 4; ++c) acc2[mt][nt][c] = 0.0f;

    #pragma unroll
    for (int kt = 0; kt < 8; ++kt) {
        uint32_t a[2][4];
        #pragma unroll
        for (int mt = 0; mt < 2; ++mt) {
            int ar = r0 + mt * 16 + gid;
            a[mt][0] = __float_as_uint(s.Xs[ar    ][kt * 8 + tig]);
            a[mt][1] = __float_as_uint(s.Xs[ar + 8][kt * 8 + tig]);
            a[mt][2] = __float_as_uint(s.Xs[ar    ][kt * 8 + tig + 4]);
            a[mt][3] = __float_as_uint(s.Xs[ar + 8][kt * 8 + tig + 4]);
        }
        #pragma unroll
        for (int nt = 0; nt < 4; ++nt) {
            uint32_t bb0 = __float_as_uint(s.W1s[nt * 8 + gid][kt * 8 + tig]);
            uint32_t bb1 = __float_as_uint(s.W1s[nt * 8 + gid][kt * 8 + tig + 4]);
            mma8(acc2[0][nt], a[0], bb0, bb1);
            mma8(acc2[1][nt], a[1], bb0, bb1);
        }
    }

    // ---- epilogue 2: e[row] = b2 + sum_c w2[c]*silu(D2[row][c]+b1[c]) ----
    {
        float b1r[4][2], w2r[4][2];
        #pragma unroll
        for (int nt = 0; nt < 4; ++nt) {
            int c0 = nt * 8 + 2 * tig;
            b1r[nt][0] = s.b1s[c0];     b1r[nt][1] = s.b1s[c0 + 1];
            w2r[nt][0] = s.w2s[c0];     w2r[nt][1] = s.w2s[c0 + 1];
        }
        const float bb2 = s.b2s;

        #pragma unroll
        for (int mt = 0; mt < 2; ++mt) {
            float elo = 0.0f, ehi = 0.0f;
            #pragma unroll
            for (int nt = 0; nt < 4; ++nt) {
                elo += w2r[nt][0] * silu_t(acc2[mt][nt][0] + b1r[nt][0]);
                elo += w2r[nt][1] * silu_t(acc2[mt][nt][1] + b1r[nt][1]);
                ehi += w2r[nt][0] * silu_t(acc2[mt][nt][2] + b1r[nt][0]);
                ehi += w2r[nt][1] * silu_t(acc2[mt][nt][3] + b1r[nt][1]);
            }
            // reduce across the 4 lanes of the quad (same row)
            #pragma unroll
            for (int off = 1; off < 4; off <<= 1) {
                elo += __shfl_xor_sync(0xffffffffu, elo, off);
                ehi += __shfl_xor_sync(0xffffffffu, ehi, off);
            }
            if (tig == 0) {
                int rlo = b0row + r0 + mt * 16 + gid;
                atomicAdd(&out[rlo],     elo + bb2);
                atomicAdd(&out[rlo + 8], ehi + bb2);
            }
        }
    }
}

extern "C" void kernel_launch(void* const* d_in, const int* in_sizes, int n_in,
                              void* d_out, int out_size)
{
    const float* x  = (const float*)d_in[0];
    const int*   an = (const int*)  d_in[1];
    const float* w0 = (const float*)d_in[2];
    const float* b0 = (const float*)d_in[3];
    const float* w1 = (const float*)d_in[4];
    const float* b1 = (const float*)d_in[5];
    const float* w2 = (const float*)d_in[6];
    const float* b2 = (const float*)d_in[7];
    float* out = (float*)d_out;

    static_assert(sizeof(Smem) < 64 * 1024, "smem too big");
    cudaFuncSetAttribute(bpnn_mma_kernel,
                         cudaFuncAttributeMaxDynamicSharedMemorySize,
                         (int)sizeof(Smem));

    zero_out_kernel<<<1, BB>>>(out);

    dim3 grid(NN, BB / BT);   // 2048 atoms x 4 batch tiles
    bpnn_mma_kernel<<<grid, THREADS, sizeof(Smem)>>>(x, an, w0, b0, w1, b1, w2, b2, out);
}

// round 5
// speedup vs baseline: 5.1667x; 1.6812x over previous
#include <cuda_runtime.h>
#include <cuda_bf16.h>
#include <cstdint>

#define BB 512
#define NN 2048
#define FF 64
#define H1 64
#define H2 32
#define BT 128
#define THREADS 128
#define XP 72            // padded row length in bf16 elems (144 B)
#define XPB 144          // row bytes

struct Smem {
    __nv_bfloat16 Xs[BT][XP];    // x tile (bf16); reused as H1 after GEMM1
    __nv_bfloat16 W0s[H1][XP];   // W0[t] rows: [out][in]
    __nv_bfloat16 W1s[H2][XP];   // W1[t] rows: [out][in]
    float b0s[H1];
    float b1s[H2];
    float w2s[H2];
    float b2s;
};

static __device__ __forceinline__ uint32_t smem_u32(const void* p) {
    uint32_t a;
    asm("{ .reg .u64 t; cvta.to.shared.u64 t, %1; cvt.u32.u64 %0, t; }" : "=r"(a) : "l"(p));
    return a;
}
static __device__ __forceinline__ uint32_t pkbf(float lo, float hi) {
    uint32_t r; asm("cvt.rn.bf16x2.f32 %0, %1, %2;" : "=r"(r) : "f"(hi), "f"(lo));
    return r;
}
static __device__ __forceinline__ float silu_t(float v) {
    float t; asm("tanh.approx.f32 %0, %1;" : "=f"(t) : "f"(0.5f * v));
    return 0.5f * v * (1.0f + t);
}
static __device__ __forceinline__ void ldsm4(uint32_t* r, uint32_t addr) {
    asm volatile("ldmatrix.sync.aligned.m8n8.x4.shared.b16 {%0,%1,%2,%3}, [%4];"
                 : "=r"(r[0]), "=r"(r[1]), "=r"(r[2]), "=r"(r[3]) : "r"(addr));
}
static __device__ __forceinline__ void mma16(float* d, const uint32_t* a,
                                             uint32_t b0r_, uint32_t b1r_) {
    asm volatile(
        "mma.sync.aligned.m16n8k16.row.col.f32.bf16.bf16.f32 "
        "{%0,%1,%2,%3}, {%4,%5,%6,%7}, {%8,%9}, {%0,%1,%2,%3};"
        : "+f"(d[0]), "+f"(d[1]), "+f"(d[2]), "+f"(d[3])
        : "r"(a[0]), "r"(a[1]), "r"(a[2]), "r"(a[3]), "r"(b0r_), "r"(b1r_));
}

__global__ void zero_out_kernel(float* __restrict__ out) {
    out[threadIdx.x] = 0.0f;
}

__global__ __launch_bounds__(THREADS)
void bpnn_bf16_kernel(const float* __restrict__ x,
                      const int*   __restrict__ atomic_numbers,
                      const float* __restrict__ w0, const float* __restrict__ b0,
                      const float* __restrict__ w1, const float* __restrict__ b1,
                      const float* __restrict__ w2, const float* __restrict__ b2,
                      float* __restrict__ out)
{
    extern __shared__ char smem_raw[];
    Smem& s = *reinterpret_cast<Smem*>(smem_raw);

    const int tid = threadIdx.x;
    const int wid = tid >> 5;
    const int lid = tid & 31;
    const int gid = lid >> 2;
    const int tig = lid & 3;
    const int n   = blockIdx.x;
    const int b0row = blockIdx.y * BT;

    const int t = atomic_numbers[n];

    // ---- stage W0 [64x64] -> bf16 ----
    {
        const float* w0p = w0 + t * H1 * FF;
        #pragma unroll
        for (int it = 0; it < 8; ++it) {
            int task = it * THREADS + tid;
            int row = task >> 4, q = task & 15;
            float4 v = *reinterpret_cast<const float4*>(&w0p[row * FF + q * 4]);
            uint2 o = make_uint2(pkbf(v.x, v.y), pkbf(v.z, v.w));
            *reinterpret_cast<uint2*>(&s.W0s[row][q * 4]) = o;
        }
    }
    // ---- stage W1 [32x64] -> bf16 ----
    {
        const float* w1p = w1 + t * H2 * H1;
        #pragma unroll
        for (int it = 0; it < 4; ++it) {
            int task = it * THREADS + tid;
            int row = task >> 4, q = task & 15;
            float4 v = *reinterpret_cast<const float4*>(&w1p[row * H1 + q * 4]);
            uint2 o = make_uint2(pkbf(v.x, v.y), pkbf(v.z, v.w));
            *reinterpret_cast<uint2*>(&s.W1s[row][q * 4]) = o;
        }
    }
    if (tid < H1) s.b0s[tid] = b0[t * H1 + tid];
    if (tid < H2) { s.b1s[tid] = b1[t * H2 + tid]; s.w2s[tid] = w2[t * H2 + tid]; }
    if (tid == 0) s.b2s = b2[t];

    // ---- stage x tile [128x64] -> bf16 ----
    #pragma unroll
    for (int it = 0; it < 16; ++it) {
        int task = it * THREADS + tid;
        int row = task >> 4, q = task & 15;
        size_t g = ((size_t)(b0row + row) * NN + n) * FF + q * 4;
        float4 v = *reinterpret_cast<const float4*>(&x[g]);
        uint2 o = make_uint2(pkbf(v.x, v.y), pkbf(v.z, v.w));
        *reinterpret_cast<uint2*>(&s.Xs[row][q * 4]) = o;
    }
    __syncthreads();

    const int r0 = wid * 32;   // warp-private 32-row slice

    // precomputed ldmatrix base addresses (per lane)
    // A (X/H1 tile): lanes 0-15 -> rows (lid&15), col 0; lanes 16-31 -> same rows, col+8
    const uint32_t aBase = smem_u32(&s.Xs[0][0]) +
        (uint32_t)(r0 + (lid & 15)) * XPB + (uint32_t)((lid >> 4) * 8) * 2;
    // B (weight tiles): rows (lid&7) + ((lid>>4)<<3); col extra ((lid>>3)&1)*8
    const uint32_t bRow = (lid & 7) + ((lid >> 4) << 3);
    const uint32_t bColB = (((lid >> 3) & 1) * 8) * 2;
    const uint32_t b0Base = smem_u32(&s.W0s[0][0]) + bRow * XPB + bColB;
    const uint32_t b1Base = smem_u32(&s.W1s[0][0]) + bRow * XPB + bColB;

    // ================= GEMM1: D1[32x64] = X . W0^T =================
    float acc[2][8][4];
    #pragma unroll
    for (int mt = 0; mt < 2; ++mt)
        #pragma unroll
        for (int nt = 0; nt < 8; ++nt)
            #pragma unroll
            for (int c = 0; c < 4; ++c) acc[mt][nt][c] = 0.0f;

    #pragma unroll
    for (int kt = 0; kt < 4; ++kt) {          // K = 4 x 16
        uint32_t a[2][4];
        ldsm4(a[0], aBase + kt * 32);
        ldsm4(a[1], aBase + 16 * XPB + kt * 32);
        #pragma unroll
        for (int np = 0; np < 4; ++np) {      // n-tile pairs (16 cols each)
            uint32_t bfr[4];
            ldsm4(bfr, b0Base + np * 16 * XPB + kt * 32);
            mma16(acc[0][2 * np    ], a[0], bfr[0], bfr[1]);
            mma16(acc[0][2 * np + 1], a[0], bfr[2], bfr[3]);
            mma16(acc[1][2 * np    ], a[1], bfr[0], bfr[1]);
            mma16(acc[1][2 * np + 1], a[1], bfr[2], bfr[3]);
        }
    }

    // ---- epilogue 1: H1 = bf16(silu(D1 + b0)) back into Xs (warp-private rows) ----
    #pragma unroll
    for (int mt = 0; mt < 2; ++mt) {
        #pragma unroll
        for (int nt = 0; nt < 8; ++nt) {
            int c0 = nt * 8 + 2 * tig;
            float bc0 = s.b0s[c0], bc1 = s.b0s[c0 + 1];
            int rlo = r0 + mt * 16 + gid;
            uint32_t lo = pkbf(silu_t(acc[mt][nt][0] + bc0), silu_t(acc[mt][nt][1] + bc1));
            uint32_t hi = pkbf(silu_t(acc[mt][nt][2] + bc0), silu_t(acc[mt][nt][3] + bc1));
            *reinterpret_cast<uint32_t*>(&s.Xs[rlo    ][c0]) = lo;
            *reinterpret_cast<uint32_t*>(&s.Xs[rlo + 8][c0]) = hi;
        }
    }
    __syncwarp();

    // ================= GEMM2: D2[32x32] = H1 . W1^T =================
    float acc2[2][4][4];
    #pragma unroll
    for (int mt = 0; mt < 2; ++mt)
        #pragma unroll
        for (int nt = 0; nt < 4; ++nt)
            #pragma unroll
            for (int c = 0; c < 4; ++c) acc2[mt][nt][c] = 0.0f;

    #pragma unroll
    for (int kt = 0; kt < 4; ++kt) {
        uint32_t a[2][4];
        ldsm4(a[0], aBase + kt * 32);
        ldsm4(a[1], aBase + 16 * XPB + kt * 32);
        #pragma unroll
        for (int np = 0; np < 2; ++np) {
            uint32_t bfr[4];
            ldsm4(bfr, b1Base + np * 16 * XPB + kt * 32);
            mma16(acc2[0][2 * np    ], a[0], bfr[0], bfr[1]);
            mma16(acc2[0][2 * np + 1], a[0], bfr[2], bfr[3]);
            mma16(acc2[1][2 * np    ], a[1], bfr[0], bfr[1]);
            mma16(acc2[1][2 * np + 1], a[1], bfr[2], bfr[3]);
        }
    }

    // ---- epilogue 2: e[row] = b2 + sum_c w2[c]*silu(D2[row][c]+b1[c]) ----
    {
        float b1r[4][2], w2r[4][2];
        #pragma unroll
        for (int nt = 0; nt < 4; ++nt) {
            int c0 = nt * 8 + 2 * tig;
            b1r[nt][0] = s.b1s[c0]; b1r[nt][1] = s.b1s[c0 + 1];
            w2r[nt][0] = s.w2s[c0]; w2r[nt][1] = s.w2s[c0 + 1];
        }
        const float bb2 = s.b2s;

        #pragma unroll
        for (int mt = 0; mt < 2; ++mt) {
            float elo = 0.0f, ehi = 0.0f;
            #pragma unroll
            for (int nt = 0; nt < 4; ++nt) {
                elo += w2r[nt][0] * silu_t(acc2[mt][nt][0] + b1r[nt][0]);
                elo += w2r[nt][1] * silu_t(acc2[mt][nt][1] + b1r[nt][1]);
                ehi += w2r[nt][0] * silu_t(acc2[mt][nt][2] + b1r[nt][0]);
                ehi += w2r[nt][1] * silu_t(acc2[mt][nt][3] + b1r[nt][1]);
            }
            #pragma unroll
            for (int off = 1; off < 4; off <<= 1) {
                elo += __shfl_xor_sync(0xffffffffu, elo, off);
                ehi += __shfl_xor_sync(0xffffffffu, ehi, off);
            }
            if (tig == 0) {
                int rlo = b0row + r0 + mt * 16 + gid;
                atomicAdd(&out[rlo],     elo + bb2);
                atomicAdd(&out[rlo + 8], ehi + bb2);
            }
        }
    }
}

extern "C" void kernel_launch(void* const* d_in, const int* in_sizes, int n_in,
                              void* d_out, int out_size)
{
    const float* x  = (const float*)d_in[0];
    const int*   an = (const int*)  d_in[1];
    const float* w0 = (const float*)d_in[2];
    const float* b0 = (const float*)d_in[3];
    const float* w1 = (const float*)d_in[4];
    const float* b1 = (const float*)d_in[5];
    const float* w2 = (const float*)d_in[6];
    const float* b2 = (const float*)d_in[7];
    float* out = (float*)d_out;

    static_assert(sizeof(Smem) < 48 * 1024, "smem too big");
    cudaFuncSetAttribute(bpnn_bf16_kernel,
                         cudaFuncAttributeMaxDynamicSharedMemorySize,
                         (int)sizeof(Smem));

    zero_out_kernel<<<1, BB>>>(out);

    dim3 grid(NN, BB / BT);   // 2048 atoms x 4 batch tiles
    bpnn_bf16_kernel<<<grid, THREADS, sizeof(Smem)>>>(x, an, w0, b0, w1, b1, w2, b2, out);
}